// round 1
// baseline (speedup 1.0000x reference)
#include <cuda_runtime.h>

#define B_ROWS    16384
#define DIMC      128
#define SUMK      4096
#define KPC       2048
#define R_TILE    16
#define GEMM_BLOCKS (B_ROWS / R_TILE)   /* 1024 */
#define REG_SLOTS (2 * 64 * 64)         /* 8192 */

// ---------------- device scratch (static, no allocation) ----------------
__device__ float g_centers[DIMC * SUMK];       // normalized centers, [d][c]
__device__ float g_ce_partial[GEMM_BLOCKS];
__device__ float g_reg_partial[REG_SLOTS];

// ---------------- f32x2 helpers ----------------
__device__ __forceinline__ unsigned long long pack2(float lo, float hi) {
    unsigned long long r;
    asm("mov.b64 %0, {%1, %2};" : "=l"(r) : "f"(lo), "f"(hi));
    return r;
}
__device__ __forceinline__ void unpack2(unsigned long long v, float& lo, float& hi) {
    asm("mov.b64 {%0, %1}, %2;" : "=f"(lo), "=f"(hi) : "l"(v));
}
#define FMA2(acc, a, b) asm("fma.rn.f32x2 %0, %1, %2, %0;" : "+l"(acc) : "l"(a), "l"(b))

// ---------------- kernel 1: normalize centers (columns of fc) ----------------
__global__ void __launch_bounds__(256) normalize_centers_kernel(const float* __restrict__ fc) {
    int c = blockIdx.x * 256 + threadIdx.x;   // grid = SUMK/256
    float ss = 0.f;
    #pragma unroll 8
    for (int d = 0; d < DIMC; d++) {
        float v = fc[d * SUMK + c];
        ss += v * v;
    }
    float rn = rsqrtf(ss);
    #pragma unroll 8
    for (int d = 0; d < DIMC; d++) {
        g_centers[d * SUMK + c] = fc[d * SUMK + c] * rn;
    }
}

// ---------------- kernel 2: fused normalize-x + GEMM + softmax-weighted sim + CE ----------------
__global__ void __launch_bounds__(256, 1) gemm_softmax_kernel(
    const float* __restrict__ x,
    const long long* __restrict__ target,
    float* __restrict__ out)
{
    __shared__ __align__(16) float xsT[DIMC][R_TILE];  // x transposed tile [d][r]
    __shared__ float ssq[R_TILE][32];
    __shared__ float rnorm[R_TILE];
    __shared__ float wz[8][R_TILE], ws[8][R_TILE];
    __shared__ float zfin[2][R_TILE], sfin[2][R_TILE];
    __shared__ float cebuf[R_TILE];

    const int tid  = threadIdx.x;
    const int row0 = blockIdx.x * R_TILE;

    // ---- stage x tile (16 rows x 128) into smem, transposed; compute row sumsq ----
    const float4* x4 = reinterpret_cast<const float4*>(x);
    #pragma unroll
    for (int k = 0; k < 2; k++) {
        int q  = k * 256 + tid;      // 0..511
        int r  = q >> 5;             // row 0..15
        int qd = q & 31;             // quad 0..31
        float4 v = x4[(row0 + r) * 32 + qd];
        xsT[qd * 4 + 0][r] = v.x;
        xsT[qd * 4 + 1][r] = v.y;
        xsT[qd * 4 + 2][r] = v.z;
        xsT[qd * 4 + 3][r] = v.w;
        ssq[r][qd] = v.x * v.x + v.y * v.y + v.z * v.z + v.w * v.w;
    }
    __syncthreads();
    if (tid < R_TILE) {
        float s = 0.f;
        #pragma unroll
        for (int q = 0; q < 32; q++) s += ssq[tid][q];
        rnorm[tid] = rsqrtf(s);
    }
    __syncthreads();
    #pragma unroll
    for (int k = 0; k < (DIMC * R_TILE) / 256; k++) {  // 8
        int i = k * 256 + tid;
        int d = i >> 4, r = i & 15;
        xsT[d][r] *= rnorm[r];
    }
    __syncthreads();

    const int lane = tid & 31, wid = tid >> 5;
    const float4* C4 = reinterpret_cast<const float4*>(g_centers);

    for (int cls = 0; cls < 2; cls++) {
        float zz[R_TILE], sv[R_TILE];
        #pragma unroll
        for (int r = 0; r < R_TILE; r++) { zz[r] = 0.f; sv[r] = 0.f; }

        for (int half = 0; half < 2; half++) {
            const int cbase = cls * KPC + half * 1024 + tid * 4;
            unsigned long long acc[8][4];
            #pragma unroll
            for (int p = 0; p < 8; p++) {
                #pragma unroll
                for (int jj = 0; jj < 4; jj++) acc[p][jj] = 0ULL;
            }

            const int cidx = cbase >> 2;
            #pragma unroll 4
            for (int d = 0; d < DIMC; d++) {
                float4 cv = C4[d * (SUMK / 4) + cidx];
                unsigned long long b0 = pack2(cv.x, cv.x);
                unsigned long long b1 = pack2(cv.y, cv.y);
                unsigned long long b2 = pack2(cv.z, cv.z);
                unsigned long long b3 = pack2(cv.w, cv.w);
                #pragma unroll
                for (int p = 0; p < 8; p++) {
                    unsigned long long xv =
                        *reinterpret_cast<const unsigned long long*>(&xsT[d][2 * p]);
                    FMA2(acc[p][0], xv, b0);
                    FMA2(acc[p][1], xv, b1);
                    FMA2(acc[p][2], xv, b2);
                    FMA2(acc[p][3], xv, b3);
                }
            }

            // convert dots -> exp accumulators (|s|<=1 so no max-shift needed)
            #pragma unroll
            for (int p = 0; p < 8; p++) {
                #pragma unroll
                for (int jj = 0; jj < 4; jj++) {
                    float lo, hi;
                    unpack2(acc[p][jj], lo, hi);
                    float e0 = __expf(10.f * lo);
                    zz[2 * p]     += e0;
                    sv[2 * p]     += e0 * lo;
                    float e1 = __expf(10.f * hi);
                    zz[2 * p + 1] += e1;
                    sv[2 * p + 1] += e1 * hi;
                }
            }
        }

        // deterministic block reduction of zz/sv per row
        #pragma unroll
        for (int r = 0; r < R_TILE; r++) {
            #pragma unroll
            for (int off = 16; off > 0; off >>= 1) {
                zz[r] += __shfl_down_sync(0xffffffffu, zz[r], off);
                sv[r] += __shfl_down_sync(0xffffffffu, sv[r], off);
            }
        }
        if (lane == 0) {
            #pragma unroll
            for (int r = 0; r < R_TILE; r++) { wz[wid][r] = zz[r]; ws[wid][r] = sv[r]; }
        }
        __syncthreads();
        if (tid < 32) {
            int r = tid & 15;
            float s = 0.f;
            if (tid < 16) {
                for (int w = 0; w < 8; w++) s += wz[w][r];
                zfin[cls][r] = s;
            } else {
                for (int w = 0; w < 8; w++) s += ws[w][r];
                sfin[cls][r] = s;
            }
        }
        __syncthreads();
    }

    // epilogue: logits + per-row CE
    if (tid < R_TILE) {
        int grow = row0 + tid;
        float sc0 = sfin[0][tid] / zfin[0][tid];
        float sc1 = sfin[1][tid] / zfin[1][tid];
        float l0 = 20.f * (sc0 - 0.01f);
        float l1 = 20.f * (sc1 - 0.01f);
        out[1 + 2 * grow + 0] = l0;
        out[1 + 2 * grow + 1] = l1;
        long long t = target[grow];
        float m = fmaxf(l0, l1);
        float lse = m + logf(expf(l0 - m) + expf(l1 - m));
        cebuf[tid] = lse - (t == 0 ? l0 : l1);
    }
    __syncthreads();
    if (tid == 0) {
        float s = 0.f;
        #pragma unroll
        for (int r = 0; r < R_TILE; r++) s += cebuf[r];
        g_ce_partial[blockIdx.x] = s;
    }
}

// ---------------- kernel 3: intra-class center-pair regularizer ----------------
__global__ void __launch_bounds__(256) pairs_kernel() {
    const int ti  = blockIdx.x, tj = blockIdx.y, cls = blockIdx.z;
    const int slot = (cls * 64 + tj) * 64 + ti;
    const int tid = threadIdx.x;
    if (tj < ti) {                       // below-diagonal tile: contributes 0
        if (tid == 0) g_reg_partial[slot] = 0.f;
        return;
    }
    __shared__ float As[DIMC][32];
    __shared__ float Bs[DIMC][32];
    const int bi = cls * KPC + ti * 32;
    const int bj = cls * KPC + tj * 32;
    for (int l = tid; l < DIMC * 32; l += 256) {
        int d = l >> 5, c = l & 31;
        As[d][c] = g_centers[d * SUMK + bi + c];
        Bs[d][c] = g_centers[d * SUMK + bj + c];
    }
    __syncthreads();

    const int j = tid & 31, i0 = tid >> 5;
    float acc[4] = {0.f, 0.f, 0.f, 0.f};
    #pragma unroll 4
    for (int d = 0; d < DIMC; d++) {
        float b = Bs[d][j];
        #pragma unroll
        for (int k = 0; k < 4; k++) acc[k] += As[d][i0 + 8 * k] * b;
    }
    float local = 0.f;
    #pragma unroll
    for (int k = 0; k < 4; k++) {
        int gi = ti * 32 + i0 + 8 * k;
        int gj = tj * 32 + j;
        if (gi < gj) local += sqrtf(fmaxf(2.00001f - 2.f * acc[k], 0.f));
    }
    #pragma unroll
    for (int off = 16; off > 0; off >>= 1)
        local += __shfl_down_sync(0xffffffffu, local, off);
    __shared__ float wsum[8];
    if ((tid & 31) == 0) wsum[tid >> 5] = local;
    __syncthreads();
    if (tid == 0) {
        float s = 0.f;
        #pragma unroll
        for (int w = 0; w < 8; w++) s += wsum[w];
        g_reg_partial[slot] = s;
    }
}

// ---------------- kernel 4: final deterministic reduction ----------------
__global__ void __launch_bounds__(256) finalize_kernel(float* __restrict__ out) {
    const int tid = threadIdx.x;
    float ce = 0.f, rg = 0.f;
    for (int i = tid; i < GEMM_BLOCKS; i += 256) ce += g_ce_partial[i];
    for (int i = tid; i < REG_SLOTS;   i += 256) rg += g_reg_partial[i];
    #pragma unroll
    for (int off = 16; off > 0; off >>= 1) {
        ce += __shfl_down_sync(0xffffffffu, ce, off);
        rg += __shfl_down_sync(0xffffffffu, rg, off);
    }
    __shared__ float sc[8], sr[8];
    if ((tid & 31) == 0) { sc[tid >> 5] = ce; sr[tid >> 5] = rg; }
    __syncthreads();
    if (tid == 0) {
        float tce = 0.f, trg = 0.f;
        #pragma unroll
        for (int w = 0; w < 8; w++) { tce += sc[w]; trg += sr[w]; }
        // N_PAIRS = 2*2048*2047/2 = 4192256 ; denom = N_PAIRS*2 = 8384512
        out[0] = tce / 16384.f + 0.2f * (trg / 8384512.f);
    }
}

// ---------------- launch ----------------
extern "C" void kernel_launch(void* const* d_in, const int* in_sizes, int n_in,
                              void* d_out, int out_size) {
    const float*     x      = (const float*)d_in[0];
    const long long* target = (const long long*)d_in[1];
    const float*     fc     = (const float*)d_in[2];
    float*           out    = (float*)d_out;

    normalize_centers_kernel<<<SUMK / 256, 256>>>(fc);
    gemm_softmax_kernel<<<GEMM_BLOCKS, 256>>>(x, target, out);
    pairs_kernel<<<dim3(64, 64, 2), 256>>>();
    finalize_kernel<<<1, 256>>>(out);
}

// round 6
// speedup vs baseline: 2.2760x; 2.2760x over previous
#include <cuda_runtime.h>
#include <cuda_bf16.h>
#include <cstdint>

#define SUMK    4096
#define DIMC    128
#define KPC     2048
#define B_ROWS  16384
#define MTILE   128
#define GRID_GEMM (B_ROWS / MTILE)   /* 128 */

#define APITCH  528                  /* bytes per A row: 256 hi + 256 lo + 16 pad */
#define ABYTES  (128 * APITCH)       /* 67584 */
#define BSTAGE  (128 * APITCH)       /* one B stage: 128 cols, same pitch */
#define REDB    (ABYTES + 2 * BSTAGE)
#define SMEM_BYTES (REDB + 8 * 128 * 4)

#define PPAD    68
#define PAIRS_SMEM (2 * 128 * PPAD * 4)
#define REG_SLOTS (2 * 32 * 32)      /* 2048 */

// ---------------- device scratch ----------------
__device__ __align__(16) float    g_centers[DIMC * SUMK];  // [d][c] fp32 (pairs kernel)
__device__ __align__(16) uint32_t g_b16[SUMK * 128];       // [c]: 64 words hi | 64 words lo
__device__ float g_ce_partial[GRID_GEMM];
__device__ float g_reg_partial[REG_SLOTS];

// ---------------- helpers ----------------
__device__ __forceinline__ uint32_t smem_u32(const void* p) {
    uint32_t a;
    asm("{ .reg .u64 t; cvta.to.shared.u64 t, %1; cvt.u32.u64 %0, t; }" : "=r"(a) : "l"(p));
    return a;
}
__device__ __forceinline__ unsigned long long pack2(float lo, float hi) {
    unsigned long long r;
    asm("mov.b64 %0, {%1, %2};" : "=l"(r) : "f"(lo), "f"(hi));
    return r;
}
__device__ __forceinline__ void unpack2(unsigned long long v, float& lo, float& hi) {
    asm("mov.b64 {%0, %1}, %2;" : "=f"(lo), "=f"(hi) : "l"(v));
}
#define FMA2(acc, a, b) asm("fma.rn.f32x2 %0, %1, %2, %0;" : "+l"(acc) : "l"(a), "l"(b))

__device__ __forceinline__ float ex2_fast(float a) {
    float e;
    asm("ex2.approx.f32 %0, %1;" : "=f"(e) : "f"(a));
    return e;
}
__device__ __forceinline__ float sqrt_fast(float a) {
    float r;
    asm("sqrt.approx.f32 %0, %1;" : "=f"(r) : "f"(a));
    return r;
}
__device__ __forceinline__ uint32_t bf16pair(float v0, float v1) {
    return (uint32_t)__bfloat16_as_ushort(__float2bfloat16(v0)) |
           ((uint32_t)__bfloat16_as_ushort(__float2bfloat16(v1)) << 16);
}

#define MMA_BF16(c, a, b) \
    asm volatile("mma.sync.aligned.m16n8k16.row.col.f32.bf16.bf16.f32 " \
        "{%0,%1,%2,%3}, {%4,%5,%6,%7}, {%8,%9}, {%0,%1,%2,%3};" \
        : "+f"((c)[0]), "+f"((c)[1]), "+f"((c)[2]), "+f"((c)[3]) \
        : "r"((a)[0]), "r"((a)[1]), "r"((a)[2]), "r"((a)[3]), \
          "r"((b)[0]), "r"((b)[1]))

#define CP_ASYNC16(dst, src) \
    asm volatile("cp.async.cg.shared.global [%0], [%1], 16;" :: "r"(dst), "l"(src) : "memory")
#define CP_COMMIT() asm volatile("cp.async.commit_group;" ::: "memory")
#define CP_WAIT1()  asm volatile("cp.async.wait_group 1;" ::: "memory")

// ---------------- kernel 1: normalize centers; fp32 + bf16 hi/lo transposed copies ----------------
__global__ void __launch_bounds__(256) normalize_centers_kernel(const float* __restrict__ fc) {
    int c = blockIdx.x * 256 + threadIdx.x;
    float ss = 0.f;
    #pragma unroll 8
    for (int d = 0; d < DIMC; d++) {
        float v = fc[d * SUMK + c];
        ss += v * v;
    }
    float rn = rsqrtf(ss);
    #pragma unroll 4
    for (int dp = 0; dp < 64; dp++) {
        float v0 = fc[(2 * dp) * SUMK + c] * rn;
        float v1 = fc[(2 * dp + 1) * SUMK + c] * rn;
        g_centers[(2 * dp) * SUMK + c] = v0;
        g_centers[(2 * dp + 1) * SUMK + c] = v1;
        float h0 = __bfloat162float(__float2bfloat16(v0));
        float h1 = __bfloat162float(__float2bfloat16(v1));
        g_b16[c * 128 + dp]      = bf16pair(h0, h1);
        g_b16[c * 128 + 64 + dp] = bf16pair(v0 - h0, v1 - h1);
    }
}

// ---------------- GEMM: bf16 3-term-split mma.sync + fused streaming softmax ----------------
__device__ __forceinline__ void prefetch_b(char* smbase, int stage, int t) {
    uint32_t db = smem_u32(smbase + ABYTES + stage * BSTAGE);
    const char* src = (const char*)g_b16 + (size_t)t * 128 * 512;
    int tid = threadIdx.x;
    #pragma unroll
    for (int it = 0; it < 16; it++) {
        int q = it * 256 + tid;          // 0..4095 (128 cols x 32 chunks)
        int col = q >> 5, ch = q & 31;
        uint32_t d = db + (uint32_t)(col * APITCH + ch * 16);
        const void* s = src + col * 512 + ch * 16;
        CP_ASYNC16(d, s);
    }
}

template <int CLS>
__device__ __forceinline__ void do_class(char* sm, int mw, int nw, int grp, int tg) {
    float zacc[4]  = {0.f, 0.f, 0.f, 0.f};
    float svacc[4] = {0.f, 0.f, 0.f, 0.f};

    #pragma unroll 1
    for (int tt = 0; tt < 16; tt++) {
        const int t = CLS * 16 + tt;
        CP_WAIT1();
        __syncthreads();
        const char* Bs = sm + ABYTES + (t & 1) * BSTAGE;

        float c[2][8][4];
        #pragma unroll
        for (int mt = 0; mt < 2; mt++)
            #pragma unroll
            for (int nt = 0; nt < 8; nt++)
                #pragma unroll
                for (int i = 0; i < 4; i++) c[mt][nt][i] = 0.f;

        #pragma unroll
        for (int kt = 0; kt < 8; kt++) {
            uint32_t ah[2][4], al[2][4];
            #pragma unroll
            for (int mt = 0; mt < 2; mt++) {
                const char* ap = sm + (mw * 32 + mt * 16 + grp) * APITCH + kt * 32 + tg * 4;
                ah[mt][0] = *(const uint32_t*)(ap);
                ah[mt][1] = *(const uint32_t*)(ap + 8 * APITCH);
                ah[mt][2] = *(const uint32_t*)(ap + 16);
                ah[mt][3] = *(const uint32_t*)(ap + 8 * APITCH + 16);
                al[mt][0] = *(const uint32_t*)(ap + 256);
                al[mt][1] = *(const uint32_t*)(ap + 8 * APITCH + 256);
                al[mt][2] = *(const uint32_t*)(ap + 256 + 16);
                al[mt][3] = *(const uint32_t*)(ap + 8 * APITCH + 256 + 16);
            }
            #pragma unroll
            for (int nt = 0; nt < 8; nt++) {
                const char* bp = Bs + (nw * 64 + nt * 8 + grp) * APITCH + kt * 32 + tg * 4;
                uint32_t bh[2], bl[2];
                bh[0] = *(const uint32_t*)(bp);
                bh[1] = *(const uint32_t*)(bp + 16);
                bl[0] = *(const uint32_t*)(bp + 256);
                bl[1] = *(const uint32_t*)(bp + 256 + 16);
                #pragma unroll
                for (int mt = 0; mt < 2; mt++) {
                    MMA_BF16(c[mt][nt], ah[mt], bh);
                    MMA_BF16(c[mt][nt], ah[mt], bl);
                    MMA_BF16(c[mt][nt], al[mt], bh);
                }
            }
        }

        __syncthreads();                       // all warps done reading stage t
        if (t + 2 < 32) prefetch_b(sm, t & 1, t + 2);
        CP_COMMIT();

        // streaming softmax accumulation: |s|<=1 so no max tracking needed
        #pragma unroll
        for (int mt = 0; mt < 2; mt++)
            #pragma unroll
            for (int nt = 0; nt < 8; nt++)
                #pragma unroll
                for (int i = 0; i < 4; i++) {
                    float s = c[mt][nt][i];
                    float e = ex2_fast(s * 14.4269504088896f);  // exp(10s)
                    int idx = mt * 2 + (i >> 1);
                    zacc[idx]  += e;
                    svacc[idx] += e * s;
                }
    }

    // reduce over tg within warp, then stash per (nw, cls)
    #pragma unroll
    for (int m = 0; m < 4; m++) {
        zacc[m]  += __shfl_xor_sync(0xffffffffu, zacc[m], 1);
        zacc[m]  += __shfl_xor_sync(0xffffffffu, zacc[m], 2);
        svacc[m] += __shfl_xor_sync(0xffffffffu, svacc[m], 1);
        svacc[m] += __shfl_xor_sync(0xffffffffu, svacc[m], 2);
    }
    if (tg == 0) {
        float* redf = (float*)(sm + REDB);
        #pragma unroll
        for (int mt = 0; mt < 2; mt++)
            #pragma unroll
            for (int rp = 0; rp < 2; rp++) {
                int m = mt * 2 + rp;
                int row = mw * 32 + mt * 16 + rp * 8 + grp;
                redf[((nw * 2 + CLS) * 2 + 0) * 128 + row] = zacc[m];
                redf[((nw * 2 + CLS) * 2 + 1) * 128 + row] = svacc[m];
            }
    }
}

__global__ void __launch_bounds__(256, 1) gemm_softmax_kernel(
    const float* __restrict__ x,
    const long long* __restrict__ target,
    float* __restrict__ out)
{
    extern __shared__ char sm[];
    const int tid = threadIdx.x;
    const int lane = tid & 31, wid = tid >> 5;
    const int mw = wid & 3, nw = wid >> 2;
    const int grp = lane >> 2, tg = lane & 3;

    // kick off B pipeline immediately (independent of A staging)
    prefetch_b(sm, 0, 0);
    CP_COMMIT();
    prefetch_b(sm, 1, 1);
    CP_COMMIT();

    // A staging: each of 256 threads owns half a row (64 floats)
    {
        int row = tid >> 1, h = tid & 1;
        const float4* xr = (const float4*)(x + ((size_t)blockIdx.x * MTILE + row) * DIMC + h * 64);
        float ss = 0.f;
        #pragma unroll
        for (int i = 0; i < 16; i++) {
            float4 v = xr[i];
            ss += v.x * v.x + v.y * v.y + v.z * v.z + v.w * v.w;
        }
        ss += __shfl_xor_sync(0xffffffffu, ss, 1);
        float rn = rsqrtf(ss);
        uint32_t* ahw = (uint32_t*)(sm + row * APITCH + h * 128);
        uint32_t* alw = (uint32_t*)(sm + row * APITCH + 256 + h * 128);
        #pragma unroll
        for (int i = 0; i < 16; i++) {
            float4 v = xr[i];
            float n0 = v.x * rn, n1 = v.y * rn, n2 = v.z * rn, n3 = v.w * rn;
            float h0 = __bfloat162float(__float2bfloat16(n0));
            float h1 = __bfloat162float(__float2bfloat16(n1));
            float h2 = __bfloat162float(__float2bfloat16(n2));
            float h3 = __bfloat162float(__float2bfloat16(n3));
            ahw[2 * i]     = bf16pair(h0, h1);
            ahw[2 * i + 1] = bf16pair(h2, h3);
            alw[2 * i]     = bf16pair(n0 - h0, n1 - h1);
            alw[2 * i + 1] = bf16pair(n2 - h2, n3 - h3);
        }
    }
    __syncthreads();

    do_class<0>(sm, mw, nw, grp, tg);
    do_class<1>(sm, mw, nw, grp, tg);
    __syncthreads();

    // per-row logits + CE (threads 0..127)
    float* redf = (float*)(sm + REDB);
    float ce = 0.f;
    if (tid < 128) {
        int row = tid;
        int grow = blockIdx.x * MTILE + row;
        float z0 = redf[0 * 128 + row] + redf[4 * 128 + row];
        float s0 = redf[1 * 128 + row] + redf[5 * 128 + row];
        float z1 = redf[2 * 128 + row] + redf[6 * 128 + row];
        float s1 = redf[3 * 128 + row] + redf[7 * 128 + row];
        float l0 = 20.f * (s0 / z0 - 0.01f);
        float l1 = 20.f * (s1 / z1 - 0.01f);
        out[1 + 2 * grow + 0] = l0;
        out[1 + 2 * grow + 1] = l1;
        long long tg64 = target[grow];
        float m = fmaxf(l0, l1);
        float lse = m + logf(expf(l0 - m) + expf(l1 - m));
        ce = lse - (tg64 == 0 ? l0 : l1);
    }
    #pragma unroll
    for (int off = 16; off > 0; off >>= 1)
        ce += __shfl_down_sync(0xffffffffu, ce, off);
    __shared__ float cw[8];
    if (lane == 0) cw[wid] = ce;
    __syncthreads();
    if (tid == 0) {
        float s = 0.f;
        #pragma unroll
        for (int w = 0; w < 8; w++) s += cw[w];
        g_ce_partial[blockIdx.x] = s;
    }
}

// ---------------- kernel 3: intra-class center-pair regularizer (64x64 tiles) ----------------
__global__ void __launch_bounds__(256) pairs_kernel() {
    extern __shared__ float ps[];           // As[128][68] then Bs[128][68]
    const int ti = blockIdx.x, tj = blockIdx.y, cls = blockIdx.z;
    const int slot = (cls * 32 + tj) * 32 + ti;
    const int tid = threadIdx.x;
    if (tj < ti) {
        if (tid == 0) g_reg_partial[slot] = 0.f;
        return;
    }
    float* As = ps;
    float* Bs = ps + 128 * PPAD;
    const int bi = cls * KPC + ti * 64;
    const int bj = cls * KPC + tj * 64;
    const float4* gc4 = (const float4*)g_centers;
    #pragma unroll
    for (int it = 0; it < 8; it++) {
        int q = it * 256 + tid;             // 0..2047
        int d = q >> 4, f4 = q & 15;
        float4 va = gc4[d * (SUMK / 4) + (bi >> 2) + f4];
        float4 vb = gc4[d * (SUMK / 4) + (bj >> 2) + f4];
        *(float4*)&As[d * PPAD + f4 * 4] = va;
        *(float4*)&Bs[d * PPAD + f4 * 4] = vb;
    }
    __syncthreads();

    const int ti4 = tid & 15, tj4 = tid >> 4;
    unsigned long long acc[4][2];
    #pragma unroll
    for (int k = 0; k < 4; k++) { acc[k][0] = 0ULL; acc[k][1] = 0ULL; }

    #pragma unroll 4
    for (int d = 0; d < 128; d++) {
        float4 av = *(const float4*)&As[d * PPAD + ti4 * 4];
        unsigned long long b01 = *(const unsigned long long*)&Bs[d * PPAD + tj4 * 4];
        unsigned long long b23 = *(const unsigned long long*)&Bs[d * PPAD + tj4 * 4 + 2];
        unsigned long long a;
        a = pack2(av.x, av.x); FMA2(acc[0][0], a, b01); FMA2(acc[0][1], a, b23);
        a = pack2(av.y, av.y); FMA2(acc[1][0], a, b01); FMA2(acc[1][1], a, b23);
        a = pack2(av.z, av.z); FMA2(acc[2][0], a, b01); FMA2(acc[2][1], a, b23);
        a = pack2(av.w, av.w); FMA2(acc[3][0], a, b01); FMA2(acc[3][1], a, b23);
    }

    float local = 0.f;
    #pragma unroll
    for (int k = 0; k < 4; k++) {
        int gi = ti * 64 + ti4 * 4 + k;
        #pragma unroll
        for (int jp = 0; jp < 2; jp++) {
            float s0, s1;
            unpack2(acc[k][jp], s0, s1);
            int gj0 = tj * 64 + tj4 * 4 + jp * 2;
            if (gi < gj0)     local += sqrt_fast(fmaxf(2.00001f - 2.f * s0, 0.f));
            if (gi < gj0 + 1) local += sqrt_fast(fmaxf(2.00001f - 2.f * s1, 0.f));
        }
    }
    #pragma unroll
    for (int off = 16; off > 0; off >>= 1)
        local += __shfl_down_sync(0xffffffffu, local, off);
    __shared__ float wsum[8];
    if ((tid & 31) == 0) wsum[tid >> 5] = local;
    __syncthreads();
    if (tid == 0) {
        float s = 0.f;
        #pragma unroll
        for (int w = 0; w < 8; w++) s += wsum[w];
        g_reg_partial[slot] = s;
    }
}

// ---------------- kernel 4: final deterministic reduction ----------------
__global__ void __launch_bounds__(256) finalize_kernel(float* __restrict__ out) {
    const int tid = threadIdx.x;
    float ce = 0.f, rg = 0.f;
    for (int i = tid; i < GRID_GEMM; i += 256) ce += g_ce_partial[i];
    for (int i = tid; i < REG_SLOTS;  i += 256) rg += g_reg_partial[i];
    #pragma unroll
    for (int off = 16; off > 0; off >>= 1) {
        ce += __shfl_down_sync(0xffffffffu, ce, off);
        rg += __shfl_down_sync(0xffffffffu, rg, off);
    }
    __shared__ float sc[8], sr[8];
    if ((tid & 31) == 0) { sc[tid >> 5] = ce; sr[tid >> 5] = rg; }
    __syncthreads();
    if (tid == 0) {
        float tce = 0.f, trg = 0.f;
        #pragma unroll
        for (int w = 0; w < 8; w++) { tce += sc[w]; trg += sr[w]; }
        // N_PAIRS = 2*2048*2047/2 = 4192256 ; denom = N_PAIRS*2 = 8384512
        out[0] = tce / 16384.f + 0.2f * (trg / 8384512.f);
    }
}

// ---------------- launch ----------------
extern "C" void kernel_launch(void* const* d_in, const int* in_sizes, int n_in,
                              void* d_out, int out_size) {
    const float*     x      = (const float*)d_in[0];
    const long long* target = (const long long*)d_in[1];
    const float*     fc     = (const float*)d_in[2];
    float*           out    = (float*)d_out;

    cudaFuncSetAttribute(gemm_softmax_kernel,
                         cudaFuncAttributeMaxDynamicSharedMemorySize, SMEM_BYTES);
    cudaFuncSetAttribute(pairs_kernel,
                         cudaFuncAttributeMaxDynamicSharedMemorySize, PAIRS_SMEM);

    normalize_centers_kernel<<<SUMK / 256, 256>>>(fc);
    gemm_softmax_kernel<<<GRID_GEMM, 256, SMEM_BYTES>>>(x, target, out);
    pairs_kernel<<<dim3(32, 32, 2), 256, PAIRS_SMEM>>>();
    finalize_kernel<<<1, 256>>>(out);
}